// round 8
// baseline (speedup 1.0000x reference)
#include <cuda_runtime.h>
#include <cstdint>

#define SEQ    2048
#define BATCH  512
#define INPT   64
#define HIDDEN 128
#define KTOT   192             // combined [x ; h] reduction dim
#define KQ     48              // per-thread k quarter
#define GBB    2               // batches per group
#define BB     4               // batches per block (2 groups)
#define NBLK   (BATCH / BB)    // 128 blocks -> 1 per SM
#define NTHR   512

// ---- packed f32x2 helpers (sm_103a) ----
__device__ __forceinline__ unsigned long long ffma2(unsigned long long a,
                                                    unsigned long long b,
                                                    unsigned long long c) {
    unsigned long long d;
    asm("fma.rn.f32x2 %0, %1, %2, %3;" : "=l"(d) : "l"(a), "l"(b), "l"(c));
    return d;
}
__device__ __forceinline__ unsigned long long add2(unsigned long long a,
                                                   unsigned long long b) {
    unsigned long long d;
    asm("add.rn.f32x2 %0, %1, %2;" : "=l"(d) : "l"(a), "l"(b));
    return d;
}
__device__ __forceinline__ unsigned long long pack2(float lo, float hi) {
    unsigned long long v;
    asm("mov.b64 %0, {%1, %2};" : "=l"(v) : "f"(lo), "f"(hi));
    return v;
}
__device__ __forceinline__ float lo_plus_hi(unsigned long long v) {
    float x, y;
    asm("mov.b64 {%0, %1}, %2;" : "=f"(x), "=f"(y) : "l"(v));
    return x + y;
}
__device__ __forceinline__ float tanh_fast(float z) {
    float az = fabsf(z);
    float e  = __expf(-2.0f * az);
    float r  = __fdividef(1.0f - e, 1.0f + e);
    return copysignf(r, z);
}
__device__ __forceinline__ void cp16(void* smem_dst, const float* gsrc) {
    unsigned dst = (unsigned)__cvta_generic_to_shared(smem_dst);
    asm volatile("cp.async.ca.shared.global [%0], [%1], 16;" :: "r"(dst), "l"(gsrc));
}
__device__ __forceinline__ void group_bar(int id) {
    asm volatile("bar.sync %0, %1;" :: "r"(id), "r"(256) : "memory");
}

// Combined weight element: c<64 -> W_ih[j][c], c>=64 -> W_hh[j][c-64]
__device__ __forceinline__ float wcomb(const float* W_ih, const float* W_hh,
                                       int j, int c) {
    return (c < INPT) ? W_ih[j * INPT + c] : W_hh[j * HIDDEN + (c - INPT)];
}

// ============================================================================
// Fused recurrence, 1 block/SM, TWO independent barrier domains per block.
// Group g (warps 8g..8g+7, named barrier g+1) owns batches 2g, 2g+1 with its
// own triple-buffered combined state u(t) = [x(t)(64) ; h(t)(128)], K=192.
// smem v[g][buf][b][kq][52]: combined index c -> region c/48, word c%48.
// Thread in group: jp = (wid&7)*8 + (lane&7) in [0,64), kq = lane>>3.
// Owns rows jp, jp+64, k-slice [kq*48,kq*48+48), both group batches:
// 24 LDS.128 (conflict-free) + 96 FMA2 per thread per step.
// x prefetched TWO steps ahead (wait_group 1 never blocks).
// ============================================================================
__global__ void __launch_bounds__(NTHR, 1)
rnn_fused_kernel(const float* __restrict__ xs,
                 const float* __restrict__ W_ih,
                 const float* __restrict__ W_hh,
                 const float* __restrict__ b_ih,
                 const float* __restrict__ b_hh,
                 const float* __restrict__ W_out,
                 const float* __restrict__ b_out,
                 float* __restrict__ out) {
    __shared__ __align__(16) float v[2][3][GBB][4][52];

    const int tid    = threadIdx.x;
    const int wid    = tid >> 5;
    const int lane   = tid & 31;
    const int g      = tid >> 8;            // group 0/1
    const int wg_tid = tid & 255;
    const int jp     = (wid & 7) * 8 + (lane & 7);
    const int kq     = lane >> 3;
    const long bbase = (long)blockIdx.x * BB;

    // final-value slot for this lane (round-6 verified reduction layout)
    const int b_st = kq & 1;                       // group-local batch
    const int j_st = (kq >= 2) ? (jp + 64) : jp;
    const int c_st = INPT + j_st;
    const int st_r = c_st / KQ;
    const int st_i = c_st % KQ;

    // weights: rows jp and jp+64, combined k-slice [kq*48, kq*48+48)
    unsigned long long w0[KQ / 2], w1[KQ / 2];
    #pragma unroll
    for (int i = 0; i < KQ / 2; i++) {
        int ca = kq * KQ + 2 * i;
        w0[i] = pack2(wcomb(W_ih, W_hh, jp,      ca),
                      wcomb(W_ih, W_hh, jp,      ca + 1));
        w1[i] = pack2(wcomb(W_ih, W_hh, jp + 64, ca),
                      wcomb(W_ih, W_hh, jp + 64, ca + 1));
    }
    const float bias = b_ih[j_st] + b_hh[j_st];

    // x chunk mapping: 16B seg -> region0 word seg*4 (seg<12),
    //                           region1 word (seg-12)*4 (seg>=12)
    auto xdst = [&](int gg, int p, int b, int seg) -> float* {
        return (seg < 12) ? &v[gg][p][b][0][seg * 4]
                          : &v[gg][p][b][1][(seg - 12) * 4];
    };

    // init: zero everything (h0 = 0); stage x(0)->buf0, x(1)->buf1, all groups
    for (int i = tid; i < 2 * 3 * GBB * 4 * 52; i += NTHR)
        (&v[0][0][0][0][0])[i] = 0.0f;
    __syncthreads();
    if (tid < BB * 16) {
        int ba = tid >> 4, seg = tid & 15;          // ba in [0,4)
        int gg = ba >> 1, bl = ba & 1;
        cp16(xdst(gg, 0, bl, seg), xs + (bbase + ba) * INPT + seg * 4);
        cp16(xdst(gg, 1, bl, seg),
             xs + ((long)BATCH + bbase + ba) * INPT + seg * 4);
    }
    asm volatile("cp.async.commit_group;" ::);
    asm volatile("cp.async.wait_group 0;" ::);
    __syncthreads();

    auto step = [&](int p0, int p1, int p2, int t) {
        // prefetch x(t+2) into buffer p2's x region (group-local)
        if (t + 2 < SEQ && wg_tid < GBB * 16) {
            int bl = wg_tid >> 4, seg = wg_tid & 15;
            cp16(xdst(g, p2, bl, seg),
                 xs + ((long)(t + 2) * BATCH + bbase + 2 * g + bl) * INPT
                    + seg * 4);
        }
        asm volatile("cp.async.commit_group;" ::);

        // 24 LDS.128, each feeding 2 j-rows: 96 FMA2
        const ulonglong2* h0 =
            reinterpret_cast<const ulonglong2*>(&v[g][p0][0][kq][0]);
        const ulonglong2* h1 =
            reinterpret_cast<const ulonglong2*>(&v[g][p0][1][kq][0]);
        unsigned long long a00 = 0, a01 = 0, a10 = 0, a11 = 0;  // b0: j0,j1
        unsigned long long a20 = 0, a21 = 0, a30 = 0, a31 = 0;  // b1: j0,j1
        #pragma unroll
        for (int i = 0; i < 6; i++) {
            ulonglong2 p  = h0[2 * i];
            ulonglong2 p2 = h0[2 * i + 1];
            ulonglong2 q  = h1[2 * i];
            ulonglong2 q2 = h1[2 * i + 1];
            a00 = ffma2(w0[4 * i],     p.x,  a00);
            a10 = ffma2(w1[4 * i],     p.x,  a10);
            a01 = ffma2(w0[4 * i + 1], p.y,  a01);
            a11 = ffma2(w1[4 * i + 1], p.y,  a11);
            a00 = ffma2(w0[4 * i + 2], p2.x, a00);
            a10 = ffma2(w1[4 * i + 2], p2.x, a10);
            a01 = ffma2(w0[4 * i + 3], p2.y, a01);
            a11 = ffma2(w1[4 * i + 3], p2.y, a11);
            a20 = ffma2(w0[4 * i],     q.x,  a20);
            a30 = ffma2(w1[4 * i],     q.x,  a30);
            a21 = ffma2(w0[4 * i + 1], q.y,  a21);
            a31 = ffma2(w1[4 * i + 1], q.y,  a31);
            a20 = ffma2(w0[4 * i + 2], q2.x, a20);
            a30 = ffma2(w1[4 * i + 2], q2.x, a30);
            a21 = ffma2(w0[4 * i + 3], q2.y, a21);
            a31 = ffma2(w1[4 * i + 3], q2.y, a31);
        }
        float s00 = lo_plus_hi(add2(a00, a01));  // (jp,    b0) over kq
        float s10 = lo_plus_hi(add2(a10, a11));  // (jp+64, b0)
        float s01 = lo_plus_hi(add2(a20, a21));  // (jp,    b1)
        float s11 = lo_plus_hi(add2(a30, a31));  // (jp+64, b1)

        // Round A (xor 8): even kq keeps b0, odd keeps b1
        const bool oddq = (kq & 1);
        float sendA0 = oddq ? s00 : s01;
        float sendA1 = oddq ? s10 : s11;
        float rA0 = __shfl_xor_sync(0xffffffffu, sendA0, 8);
        float rA1 = __shfl_xor_sync(0xffffffffu, sendA1, 8);
        float S0 = (oddq ? s01 : s00) + rA0;   // (jp,    b_st) over k-half
        float S1 = (oddq ? s11 : s10) + rA1;   // (jp+64, b_st)

        // Round B (xor 16): kq<2 keeps jp, kq>=2 keeps jp+64
        const bool hiq = (kq >= 2);
        float sendB = hiq ? S0 : S1;
        float rB = __shfl_xor_sync(0xffffffffu, sendB, 16);
        float z = (hiq ? S1 : S0) + rB + bias;

        v[g][p1][b_st][st_r][st_i] = tanh_fast(z);

        asm volatile("cp.async.wait_group 1;" ::);  // x(t+1), committed last step
        group_bar(g + 1);
    };

    // 2046 steps in rotations of 3, then 2 tail steps. Final h in buffer 2.
    for (int t = 0; t < SEQ - 2; t += 3) {
        step(0, 1, 2, t);
        step(1, 2, 0, t + 1);
        step(2, 0, 1, t + 2);
    }
    step(0, 1, 2, SEQ - 2);
    step(1, 2, 0, SEQ - 1);

    // output projection (per group): out[2g+b] = h_final . W_out + b_out
    if (wg_tid < GBB * 32) {
        int bl = wg_tid >> 5, l = wg_tid & 31;
        float sacc = 0.0f;
        #pragma unroll
        for (int m = 0; m < 4; m++) {
            int jj = l + 32 * m;
            int c  = INPT + jj;
            sacc += v[g][2][bl][c / KQ][c % KQ] * W_out[jj];
        }
        #pragma unroll
        for (int off = 16; off; off >>= 1)
            sacc += __shfl_down_sync(0xffffffffu, sacc, off);
        if (l == 0) out[bbase + 2 * g + bl] = sacc + b_out[0];
    }
}

extern "C" void kernel_launch(void* const* d_in, const int* in_sizes, int n_in,
                              void* d_out, int out_size) {
    const float* xs    = (const float*)d_in[0];
    const float* W_ih  = (const float*)d_in[1];
    const float* W_hh  = (const float*)d_in[2];
    const float* b_ih  = (const float*)d_in[3];
    const float* b_hh  = (const float*)d_in[4];
    const float* W_out = (const float*)d_in[5];
    const float* b_out = (const float*)d_in[6];

    rnn_fused_kernel<<<NBLK, NTHR>>>(xs, W_ih, W_hh, b_ih, b_hh, W_out, b_out,
                                     (float*)d_out);
}